// round 4
// baseline (speedup 1.0000x reference)
// THEORY (round 4): prior rounds never benched real code (extractor pulled
// prose into the .cu). This round: whole response is one self-contained
// ASCII-only .cu. Pipeline and cost model (B=8, N=8192, S=2048, K=32):
//  1. fps_kernel: serial 2048-round argmax, 1 block/batch (8 SMs busy).
//     xyz in 96KB SMEM, 8 pts/thread in regs, two-level shfl argmax,
//     2 barriers/iter -> ~1100 cyc/iter -> ~1.1-1.3 ms. Dominant; attack later.
//     Distance via __fmul_rn/__fadd_rn (no fma contraction) to match XLA
//     sum((x-c)^2) and avoid argmax tie flips.
//  2. ball_kernel: warp/centroid streaming "32 nearest within radius, fill
//     with nearest" == reference top_k+replace as a SET (downstream maxpool
//     is order/duplicate invariant; centroid itself guarantees >=1 in-radius).
//     ~200 us.
//  3. mlp_kernel: fused gather + 3-layer MLP (BN folded by prep_kernel,
//     weights transposed [cin][cout] for float4 SMEM broadcasts) + maxpool.
//     Lane = sample point, activations register-resident, ReLU commuted past
//     max. ~12.9K FMA/point -> FFMA-pipe bound ~400 us.
// PREDICTION: passes, rel_err <= 1e-4, dur_us ~ 1700-2000. ncu: fps_kernel
// top (issue-bound, 8/148 SMs), mlp_kernel near fma-pipe roofline.

#include <cuda_runtime.h>

#define NB 8
#define NN 8192
#define NS 2048

// folded weights: w0t[9*64]@0 b0@576 w1t[64*64]@640 b1@4736 w2t[64*128]@4800 b2@12992
__device__ __align__(16) float g_w[13120];
__device__ int g_ball[NB * NS * 32];

__global__ void prep_kernel(const float* w0, const float* b0, const float* g0, const float* bt0, const float* m0, const float* v0,
                            const float* w1, const float* b1, const float* g1, const float* bt1, const float* m1, const float* v1,
                            const float* w2, const float* b2, const float* g2, const float* bt2, const float* m2, const float* v2) {
    int t = threadIdx.x;
    if (t < 64) {
        float s = g0[t] * rsqrtf(v0[t] + 1e-5f);
        for (int c = 0; c < 9; c++) g_w[c * 64 + t] = w0[t * 9 + c] * s;
        g_w[576 + t] = (b0[t] - m0[t]) * s + bt0[t];
        float s1 = g1[t] * rsqrtf(v1[t] + 1e-5f);
        for (int c = 0; c < 64; c++) g_w[640 + c * 64 + t] = w1[t * 64 + c] * s1;
        g_w[4736 + t] = (b1[t] - m1[t]) * s1 + bt1[t];
    }
    if (t < 128) {
        float s2 = g2[t] * rsqrtf(v2[t] + 1e-5f);
        for (int c = 0; c < 64; c++) g_w[4800 + c * 128 + t] = w2[t * 64 + c] * s2;
        g_w[12992 + t] = (b2[t] - m2[t]) * s2 + bt2[t];
    }
}

__global__ __launch_bounds__(1024, 1) void fps_kernel(const float* __restrict__ xyz, float* __restrict__ nxyz) {
    extern __shared__ float sx[];            // 24576 floats
    __shared__ float swv[32];
    __shared__ int swi[32], s_far;
    int b = blockIdx.x, t = threadIdx.x;
    const float4* src = (const float4*)(xyz + (size_t)b * NN * 3);
    float4* d4 = (float4*)sx;
    for (int i = t; i < 6144; i += 1024) d4[i] = src[i];
    __syncthreads();
    float px[8], py[8], pz[8], dd[8];
#pragma unroll
    for (int j = 0; j < 8; j++) {
        int p = t + (j << 10);
        px[j] = sx[p * 3]; py[j] = sx[p * 3 + 1]; pz[j] = sx[p * 3 + 2];
        dd[j] = 1e10f;
    }
    int far = 0;
    float* ob = nxyz + (size_t)b * NS * 3;
    for (int it = 0; it < NS; it++) {
        float cx = sx[far * 3], cy = sx[far * 3 + 1], cz = sx[far * 3 + 2];
        if (t == 0) { ob[it * 3] = cx; ob[it * 3 + 1] = cy; ob[it * 3 + 2] = cz; }
        float bv = -1.f; int bp = 0;
#pragma unroll
        for (int j = 0; j < 8; j++) {
            float dx = px[j] - cx, dy = py[j] - cy, dz = pz[j] - cz;
            float d = __fadd_rn(__fadd_rn(__fmul_rn(dx, dx), __fmul_rn(dy, dy)), __fmul_rn(dz, dz));
            float nd = fminf(dd[j], d);
            dd[j] = nd;
            if (nd > bv) { bv = nd; bp = t + (j << 10); }
        }
#pragma unroll
        for (int o = 16; o; o >>= 1) {
            float ov = __shfl_down_sync(~0u, bv, o);
            int op = __shfl_down_sync(~0u, bp, o);
            if (ov > bv || (ov == bv && op < bp)) { bv = ov; bp = op; }
        }
        if ((t & 31) == 0) { swv[t >> 5] = bv; swi[t >> 5] = bp; }
        __syncthreads();
        if (t < 32) {
            bv = swv[t]; bp = swi[t];
#pragma unroll
            for (int o = 16; o; o >>= 1) {
                float ov = __shfl_down_sync(~0u, bv, o);
                int op = __shfl_down_sync(~0u, bp, o);
                if (ov > bv || (ov == bv && op < bp)) { bv = ov; bp = op; }
            }
            if (t == 0) s_far = bp;
        }
        __syncthreads();
        far = s_far;
    }
}

__global__ __launch_bounds__(256) void ball_kernel(const float* __restrict__ xyz, const float* __restrict__ nxyz) {
    __shared__ float tile[6144];
    int b = blockIdx.x >> 8;
    int s = ((blockIdx.x & 255) << 3) + (threadIdx.x >> 5);
    int lane = threadIdx.x & 31;
    const float* nx = nxyz + (size_t)(b * NS + s) * 3;
    float cx = nx[0], cy = nx[1], cz = nx[2];
    float sn = cx * cx + cy * cy + cz * cz;
    const float R2 = 0.0625f, BIG = 1e30f;
    float kd = BIG; int ki = 0;
    float thr = BIG;
    for (int n0 = 0; n0 < NN; n0 += 2048) {
        __syncthreads();
        const float4* src = (const float4*)(xyz + (size_t)b * NN * 3 + n0 * 3);
        float4* d4 = (float4*)tile;
        for (int i = threadIdx.x; i < 1536; i += 256) d4[i] = src[i];
        __syncthreads();
        for (int c = 0; c < 2048; c += 32) {
            int p = c + lane;
            float x = tile[p * 3], y = tile[p * 3 + 1], z = tile[p * 3 + 2];
            float sp = x * x + y * y + z * z;
            float dot = x * cx + y * cy + z * cz;
            float d2 = sn + sp - 2.f * dot;
            unsigned m = __ballot_sync(~0u, d2 <= R2 && d2 < thr);
            while (m) {
                int sl = __ffs(m) - 1; m &= m - 1;
                float dv = __shfl_sync(~0u, d2, sl);
                if (dv < thr) {
                    float mv = kd; int mi = ki, ml = lane;
#pragma unroll
                    for (int o = 16; o; o >>= 1) {
                        float ov = __shfl_xor_sync(~0u, mv, o);
                        int oi = __shfl_xor_sync(~0u, mi, o);
                        int ol = __shfl_xor_sync(~0u, ml, o);
                        if (ov > mv || (ov == mv && (oi > mi || (oi == mi && ol > ml)))) { mv = ov; mi = oi; ml = ol; }
                    }
                    if (lane == ml) { kd = dv; ki = n0 + c + sl; }
                    float tv = kd;
#pragma unroll
                    for (int o = 16; o; o >>= 1) tv = fmaxf(tv, __shfl_xor_sync(~0u, tv, o));
                    thr = tv;
                }
            }
        }
    }
    float nv = kd; int ni = ki;
#pragma unroll
    for (int o = 16; o; o >>= 1) {
        float ov = __shfl_xor_sync(~0u, nv, o);
        int oi = __shfl_xor_sync(~0u, ni, o);
        if (ov < nv || (ov == nv && oi < ni)) { nv = ov; ni = oi; }
    }
    g_ball[((b * NS + s) << 5) + lane] = (kd >= BIG) ? ni : ki;
}

__global__ __launch_bounds__(256, 1) void mlp_kernel(const float* __restrict__ xyz, const float* __restrict__ pts,
                                                     const float* __restrict__ nxyz, float* __restrict__ outp) {
    __shared__ __align__(16) float W[8448];
    int b = blockIdx.x >> 8;
    int warp = threadIdx.x >> 5, lane = threadIdx.x & 31;
    int s = ((blockIdx.x & 255) << 3) + warp;
    {   // phase A: w0t,b0,w1t,b1 = 4800 floats
        const float4* g4 = (const float4*)g_w;
        float4* w4 = (float4*)W;
        for (int i = threadIdx.x; i < 1200; i += 256) w4[i] = g4[i];
    }
    int gi = g_ball[((b * NS + s) << 5) + lane];
    const float* nx = nxyz + (size_t)(b * NS + s) * 3;
    const float* P = xyz + (size_t)(b * NN + gi) * 3;
    const float2* Q = (const float2*)(pts + (size_t)(b * NN + gi) * 6);
    float f[9];
    f[0] = P[0] - nx[0]; f[1] = P[1] - nx[1]; f[2] = P[2] - nx[2];
    float2 q0 = Q[0], q1 = Q[1], q2 = Q[2];
    f[3] = q0.x; f[4] = q0.y; f[5] = q1.x; f[6] = q1.y; f[7] = q2.x; f[8] = q2.y;
    __syncthreads();

    float a[64];
    {   // layer1 9->64
        const float4* Bv = (const float4*)(W + 576);
#pragma unroll
        for (int q = 0; q < 16; q++) { float4 v = Bv[q]; a[4 * q] = v.x; a[4 * q + 1] = v.y; a[4 * q + 2] = v.z; a[4 * q + 3] = v.w; }
#pragma unroll
        for (int c = 0; c < 9; c++) {
            float xv = f[c];
            const float4* wr = (const float4*)(W + c * 64);
#pragma unroll
            for (int q = 0; q < 16; q++) {
                float4 w = wr[q];
                a[4 * q] = fmaf(xv, w.x, a[4 * q]); a[4 * q + 1] = fmaf(xv, w.y, a[4 * q + 1]);
                a[4 * q + 2] = fmaf(xv, w.z, a[4 * q + 2]); a[4 * q + 3] = fmaf(xv, w.w, a[4 * q + 3]);
            }
        }
#pragma unroll
        for (int o = 0; o < 64; o++) a[o] = fmaxf(a[o], 0.f);
    }
    {   // layer2 64->64
        float c2[64];
        const float4* Bv = (const float4*)(W + 4736);
#pragma unroll
        for (int q = 0; q < 16; q++) { float4 v = Bv[q]; c2[4 * q] = v.x; c2[4 * q + 1] = v.y; c2[4 * q + 2] = v.z; c2[4 * q + 3] = v.w; }
#pragma unroll 4
        for (int c = 0; c < 64; c++) {
            float xv = a[c];
            const float4* wr = (const float4*)(W + 640 + c * 64);
#pragma unroll
            for (int q = 0; q < 16; q++) {
                float4 w = wr[q];
                c2[4 * q] = fmaf(xv, w.x, c2[4 * q]); c2[4 * q + 1] = fmaf(xv, w.y, c2[4 * q + 1]);
                c2[4 * q + 2] = fmaf(xv, w.z, c2[4 * q + 2]); c2[4 * q + 3] = fmaf(xv, w.w, c2[4 * q + 3]);
            }
        }
#pragma unroll
        for (int o = 0; o < 64; o++) a[o] = fmaxf(c2[o], 0.f);
    }
    __syncthreads();
    {   // phase B: w2t,b2 = 8320 floats
        const float4* g4 = (const float4*)(g_w + 4800);
        float4* w4 = (float4*)W;
        for (int i = threadIdx.x; i < 2080; i += 256) w4[i] = g4[i];
    }
    __syncthreads();
    float* orow = outp + (size_t)(b * NS + s) * 128;
#pragma unroll 1
    for (int h = 0; h < 4; h++) {   // layer3 64->128, 32 ch at a time, + maxpool
        float acc[32];
        const float4* Bv = (const float4*)(W + 8192 + h * 32);
#pragma unroll
        for (int q = 0; q < 8; q++) { float4 v = Bv[q]; acc[4 * q] = v.x; acc[4 * q + 1] = v.y; acc[4 * q + 2] = v.z; acc[4 * q + 3] = v.w; }
#pragma unroll 4
        for (int c = 0; c < 64; c++) {
            float xv = a[c];
            const float4* wr = (const float4*)(W + c * 128 + h * 32);
#pragma unroll
            for (int q = 0; q < 8; q++) {
                float4 w = wr[q];
                acc[4 * q] = fmaf(xv, w.x, acc[4 * q]); acc[4 * q + 1] = fmaf(xv, w.y, acc[4 * q + 1]);
                acc[4 * q + 2] = fmaf(xv, w.z, acc[4 * q + 2]); acc[4 * q + 3] = fmaf(xv, w.w, acc[4 * q + 3]);
            }
        }
#pragma unroll
        for (int ch = 0; ch < 32; ch++)
#pragma unroll
            for (int o = 16; o; o >>= 1) acc[ch] = fmaxf(acc[ch], __shfl_xor_sync(~0u, acc[ch], o));
        float val = acc[0];
#pragma unroll
        for (int ch = 1; ch < 32; ch++) if (lane == ch) val = acc[ch];
        orow[h * 32 + lane] = fmaxf(val, 0.f);
    }
}

extern "C" void kernel_launch(void* const* d_in, const int* in_sizes, int n_in,
                              void* d_out, int out_size) {
    const float* xyz = (const float*)d_in[0];
    const float* pts = (const float*)d_in[1];
    float* out = (float*)d_out;
    float* nxyz = out;                       // (B,S,3)
    float* npts = out + NB * NS * 3;         // (B,S,128)
    cudaFuncSetAttribute(fps_kernel, cudaFuncAttributeMaxDynamicSharedMemorySize, 98304);
    prep_kernel<<<1, 128>>>((const float*)d_in[2], (const float*)d_in[3], (const float*)d_in[4],
                            (const float*)d_in[5], (const float*)d_in[6], (const float*)d_in[7],
                            (const float*)d_in[8], (const float*)d_in[9], (const float*)d_in[10],
                            (const float*)d_in[11], (const float*)d_in[12], (const float*)d_in[13],
                            (const float*)d_in[14], (const float*)d_in[15], (const float*)d_in[16],
                            (const float*)d_in[17], (const float*)d_in[18], (const float*)d_in[19]);
    fps_kernel<<<NB, 1024, 98304>>>(xyz, nxyz);
    ball_kernel<<<NB * 256, 256>>>(xyz, nxyz);
    mlp_kernel<<<NB * 256, 256>>>(xyz, pts, nxyz, npts);
}

// round 5
// speedup vs baseline: 1.2207x; 1.2207x over previous
// Round 5: packed f32x2 FPS + value-only argmax w/ equality rescan; packed f32x2 MLP.
#include <cuda_runtime.h>

#define NB 8
#define NN 8192
#define NS 2048

typedef unsigned long long u64;

#define PK2(d, lo, hi)   asm("mov.b64 %0, {%1,%2};" : "=l"(d) : "f"(lo), "f"(hi))
#define UPK2(lo, hi, v)  asm("mov.b64 {%0,%1}, %2;" : "=f"(lo), "=f"(hi) : "l"(v))
#define ADD2(d, a, b)    asm("add.rn.f32x2 %0, %1, %2;" : "=l"(d) : "l"(a), "l"(b))
#define MUL2(d, a, b)    asm("mul.rn.f32x2 %0, %1, %2;" : "=l"(d) : "l"(a), "l"(b))
#define FMA2(d, a, b, c) asm("fma.rn.f32x2 %0, %1, %2, %3;" : "=l"(d) : "l"(a), "l"(b), "l"(c))

// folded weights: w0t[9*64]@0 b0@576 w1t[64*64]@640 b1@4736 w2t[64*128]@4800 b2@12992
__device__ __align__(16) float g_w[13120];
__device__ int g_ball[NB * NS * 32];

__global__ void prep_kernel(const float* w0, const float* b0, const float* g0, const float* bt0, const float* m0, const float* v0,
                            const float* w1, const float* b1, const float* g1, const float* bt1, const float* m1, const float* v1,
                            const float* w2, const float* b2, const float* g2, const float* bt2, const float* m2, const float* v2) {
    int t = threadIdx.x;
    if (t < 64) {
        float s = g0[t] * rsqrtf(v0[t] + 1e-5f);
        for (int c = 0; c < 9; c++) g_w[c * 64 + t] = w0[t * 9 + c] * s;
        g_w[576 + t] = (b0[t] - m0[t]) * s + bt0[t];
        float s1 = g1[t] * rsqrtf(v1[t] + 1e-5f);
        for (int c = 0; c < 64; c++) g_w[640 + c * 64 + t] = w1[t * 64 + c] * s1;
        g_w[4736 + t] = (b1[t] - m1[t]) * s1 + bt1[t];
    }
    if (t < 128) {
        float s2 = g2[t] * rsqrtf(v2[t] + 1e-5f);
        for (int c = 0; c < 64; c++) g_w[4800 + c * 128 + t] = w2[t * 64 + c] * s2;
        g_w[12992 + t] = (b2[t] - m2[t]) * s2 + bt2[t];
    }
}

__global__ __launch_bounds__(1024, 1) void fps_kernel(const float* __restrict__ xyz, float* __restrict__ nxyz) {
    extern __shared__ float sx[];            // 24576 floats
    __shared__ float swv[32];
    __shared__ float s_bv;
    __shared__ int s_idx[3];
    int b = blockIdx.x, t = threadIdx.x;
    if (t == 0) { s_idx[0] = 0x7fffffff; s_idx[1] = 0x7fffffff; s_idx[2] = 0x7fffffff; }
    const float4* src = (const float4*)(xyz + (size_t)b * NN * 3);
    float4* d4 = (float4*)sx;
    for (int i = t; i < 6144; i += 1024) d4[i] = src[i];
    __syncthreads();
    // pair j holds points p0 = t + (2j)*1024 (lo) and p1 = p0 + 1024 (hi)
    u64 px2[4], py2[4], pz2[4];
    float dd[8];
#pragma unroll
    for (int j = 0; j < 4; j++) {
        int p0 = t + ((2 * j) << 10), p1 = p0 + 1024;
        PK2(px2[j], sx[p0 * 3 + 0], sx[p1 * 3 + 0]);
        PK2(py2[j], sx[p0 * 3 + 1], sx[p1 * 3 + 1]);
        PK2(pz2[j], sx[p0 * 3 + 2], sx[p1 * 3 + 2]);
        dd[2 * j] = 1e10f; dd[2 * j + 1] = 1e10f;
    }
    int far = 0;
    float* ob = nxyz + (size_t)b * NS * 3;
    for (int it = 0; it < NS; it++) {
        float cx = sx[far * 3], cy = sx[far * 3 + 1], cz = sx[far * 3 + 2];
        if (t == 0) { ob[it * 3] = cx; ob[it * 3 + 1] = cy; ob[it * 3 + 2] = cz; }
        float ncx = -cx, ncy = -cy, ncz = -cz;
        u64 ncx2, ncy2, ncz2;
        PK2(ncx2, ncx, ncx); PK2(ncy2, ncy, ncy); PK2(ncz2, ncz, ncz);
        float bv = -1.f;
#pragma unroll
        for (int j = 0; j < 4; j++) {
            u64 dx, dy, dz, xx, yy, zz, s01;
            ADD2(dx, px2[j], ncx2);        // px - cx (exact: a + (-b) == a - b)
            ADD2(dy, py2[j], ncy2);
            ADD2(dz, pz2[j], ncz2);
            MUL2(xx, dx, dx);
            MUL2(yy, dy, dy);
            MUL2(zz, dz, dz);
            ADD2(s01, xx, yy);
            ADD2(s01, s01, zz);            // (x2+y2)+z2, same association as scalar version
            float s0, s1;
            UPK2(s0, s1, s01);
            dd[2 * j]     = fminf(dd[2 * j], s0);
            dd[2 * j + 1] = fminf(dd[2 * j + 1], s1);
            bv = fmaxf(bv, dd[2 * j]);
            bv = fmaxf(bv, dd[2 * j + 1]);
        }
        float mymax = bv;
#pragma unroll
        for (int o = 16; o; o >>= 1) bv = fmaxf(bv, __shfl_xor_sync(~0u, bv, o));
        if ((t & 31) == 0) swv[t >> 5] = bv;
        __syncthreads();                               // bar A
        if (t < 32) {
            float v = swv[t];
#pragma unroll
            for (int o = 16; o; o >>= 1) v = fmaxf(v, __shfl_xor_sync(~0u, v, o));
            if (t == 0) {
                s_bv = v;
                s_idx[(it + 1) % 3] = 0x7fffffff;      // reset next iteration's slot
            }
        }
        __syncthreads();                               // bar B
        float bb = s_bv;
        if (mymax == bb) {
            int p = 0x7fffffff;
#pragma unroll
            for (int k = 7; k >= 0; k--)
                if (dd[k] == bb) p = t + (k << 10);    // descending -> keeps smallest k
            atomicMin(&s_idx[it % 3], p);
        }
        __syncthreads();                               // bar C
        far = s_idx[it % 3];
    }
}

__global__ __launch_bounds__(256) void ball_kernel(const float* __restrict__ xyz, const float* __restrict__ nxyz) {
    __shared__ float tile[6144];
    int b = blockIdx.x >> 8;
    int s = ((blockIdx.x & 255) << 3) + (threadIdx.x >> 5);
    int lane = threadIdx.x & 31;
    const float* nx = nxyz + (size_t)(b * NS + s) * 3;
    float cx = nx[0], cy = nx[1], cz = nx[2];
    float sn = cx * cx + cy * cy + cz * cz;
    const float R2 = 0.0625f, BIG = 1e30f;
    float kd = BIG; int ki = 0;
    float thr = BIG;
    for (int n0 = 0; n0 < NN; n0 += 2048) {
        __syncthreads();
        const float4* src = (const float4*)(xyz + (size_t)b * NN * 3 + n0 * 3);
        float4* d4 = (float4*)tile;
        for (int i = threadIdx.x; i < 1536; i += 256) d4[i] = src[i];
        __syncthreads();
        for (int c = 0; c < 2048; c += 32) {
            int p = c + lane;
            float x = tile[p * 3], y = tile[p * 3 + 1], z = tile[p * 3 + 2];
            float sp = x * x + y * y + z * z;
            float dot = x * cx + y * cy + z * cz;
            float d2 = sn + sp - 2.f * dot;
            unsigned m = __ballot_sync(~0u, d2 <= R2 && d2 < thr);
            while (m) {
                int sl = __ffs(m) - 1; m &= m - 1;
                float dv = __shfl_sync(~0u, d2, sl);
                if (dv < thr) {
                    float mv = kd; int mi = ki, ml = lane;
#pragma unroll
                    for (int o = 16; o; o >>= 1) {
                        float ov = __shfl_xor_sync(~0u, mv, o);
                        int oi = __shfl_xor_sync(~0u, mi, o);
                        int ol = __shfl_xor_sync(~0u, ml, o);
                        if (ov > mv || (ov == mv && (oi > mi || (oi == mi && ol > ml)))) { mv = ov; mi = oi; ml = ol; }
                    }
                    if (lane == ml) { kd = dv; ki = n0 + c + sl; }
                    float tv = kd;
#pragma unroll
                    for (int o = 16; o; o >>= 1) tv = fmaxf(tv, __shfl_xor_sync(~0u, tv, o));
                    thr = tv;
                }
            }
        }
    }
    float nv = kd; int ni = ki;
#pragma unroll
    for (int o = 16; o; o >>= 1) {
        float ov = __shfl_xor_sync(~0u, nv, o);
        int oi = __shfl_xor_sync(~0u, ni, o);
        if (ov < nv || (ov == nv && oi < ni)) { nv = ov; ni = oi; }
    }
    g_ball[((b * NS + s) << 5) + lane] = (kd >= BIG) ? ni : ki;
}

// SMEM: W[8448] weights | A[8 warps][64][32] activations (per-lane, conflict-free)
__global__ __launch_bounds__(256, 1) void mlp_kernel(const float* __restrict__ xyz, const float* __restrict__ pts,
                                                     const float* __restrict__ nxyz, float* __restrict__ outp) {
    extern __shared__ float S[];
    float* W = S;
    int b = blockIdx.x >> 8;
    int warp = threadIdx.x >> 5, lane = threadIdx.x & 31;
    int s = ((blockIdx.x & 255) << 3) + warp;
    float* A = S + 8448 + warp * 2048;
    {   // phase A: w0t,b0,w1t,b1 = 4800 floats
        const float4* g4 = (const float4*)g_w;
        float4* w4 = (float4*)W;
        for (int i = threadIdx.x; i < 1200; i += 256) w4[i] = g4[i];
    }
    int gi = g_ball[((b * NS + s) << 5) + lane];
    const float* nx = nxyz + (size_t)(b * NS + s) * 3;
    const float* P = xyz + (size_t)(b * NN + gi) * 3;
    const float2* Q = (const float2*)(pts + (size_t)(b * NN + gi) * 6);
    float f[9];
    f[0] = P[0] - nx[0]; f[1] = P[1] - nx[1]; f[2] = P[2] - nx[2];
    float2 q0 = Q[0], q1 = Q[1], q2 = Q[2];
    f[3] = q0.x; f[4] = q0.y; f[5] = q1.x; f[6] = q1.y; f[7] = q2.x; f[8] = q2.y;
    __syncthreads();

    u64 acc[32];
    {   // layer1 9->64 (acc[q] = couts 2q,2q+1)
        const u64* bp = (const u64*)(W + 576);
#pragma unroll
        for (int q = 0; q < 32; q++) acc[q] = bp[q];
#pragma unroll
        for (int c = 0; c < 9; c++) {
            u64 xx; PK2(xx, f[c], f[c]);
            const ulonglong2* wr = (const ulonglong2*)(W + c * 64);
#pragma unroll
            for (int q = 0; q < 16; q++) {
                ulonglong2 w = wr[q];
                FMA2(acc[2 * q], xx, w.x, acc[2 * q]);
                FMA2(acc[2 * q + 1], xx, w.y, acc[2 * q + 1]);
            }
        }
#pragma unroll
        for (int q = 0; q < 32; q++) {
            float r0, r1; UPK2(r0, r1, acc[q]);
            A[(2 * q) * 32 + lane]     = fmaxf(r0, 0.f);
            A[(2 * q + 1) * 32 + lane] = fmaxf(r1, 0.f);
        }
    }
    {   // layer2 64->64
        const u64* bp = (const u64*)(W + 4736);
#pragma unroll
        for (int q = 0; q < 32; q++) acc[q] = bp[q];
#pragma unroll 8
        for (int c = 0; c < 64; c++) {
            float xv = A[c * 32 + lane];
            u64 xx; PK2(xx, xv, xv);
            const ulonglong2* wr = (const ulonglong2*)(W + 640 + c * 64);
#pragma unroll
            for (int q = 0; q < 16; q++) {
                ulonglong2 w = wr[q];
                FMA2(acc[2 * q], xx, w.x, acc[2 * q]);
                FMA2(acc[2 * q + 1], xx, w.y, acc[2 * q + 1]);
            }
        }
#pragma unroll
        for (int q = 0; q < 32; q++) {
            float r0, r1; UPK2(r0, r1, acc[q]);
            A[(2 * q) * 32 + lane]     = fmaxf(r0, 0.f);
            A[(2 * q + 1) * 32 + lane] = fmaxf(r1, 0.f);
        }
    }
    __syncthreads();
    {   // phase B: w2t,b2 = 8320 floats
        const float4* g4 = (const float4*)(g_w + 4800);
        float4* w4 = (float4*)W;
        for (int i = threadIdx.x; i < 2080; i += 256) w4[i] = g4[i];
    }
    __syncthreads();
    float* orow = outp + (size_t)(b * NS + s) * 128;
#pragma unroll 1
    for (int h = 0; h < 2; h++) {   // layer3 64->128 in two 64-cout halves, + maxpool
        const u64* bp = (const u64*)(W + 8192 + h * 64);
#pragma unroll
        for (int q = 0; q < 32; q++) acc[q] = bp[q];
#pragma unroll 8
        for (int c = 0; c < 64; c++) {
            float xv = A[c * 32 + lane];
            u64 xx; PK2(xx, xv, xv);
            const ulonglong2* wr = (const ulonglong2*)(W + c * 128 + h * 64);
#pragma unroll
            for (int q = 0; q < 16; q++) {
                ulonglong2 w = wr[q];
                FMA2(acc[2 * q], xx, w.x, acc[2 * q]);
                FMA2(acc[2 * q + 1], xx, w.y, acc[2 * q + 1]);
            }
        }
        float2 mv;
#pragma unroll
        for (int q = 0; q < 32; q++) {
            float r0, r1; UPK2(r0, r1, acc[q]);
#pragma unroll
            for (int o = 16; o; o >>= 1) {
                r0 = fmaxf(r0, __shfl_xor_sync(~0u, r0, o));
                r1 = fmaxf(r1, __shfl_xor_sync(~0u, r1, o));
            }
            if (lane == q) { mv.x = fmaxf(r0, 0.f); mv.y = fmaxf(r1, 0.f); }
        }
        ((float2*)orow)[h * 32 + lane] = mv;
    }
}

extern "C" void kernel_launch(void* const* d_in, const int* in_sizes, int n_in,
                              void* d_out, int out_size) {
    const float* xyz = (const float*)d_in[0];
    const float* pts = (const float*)d_in[1];
    float* out = (float*)d_out;
    float* nxyz = out;                       // (B,S,3)
    float* npts = out + NB * NS * 3;         // (B,S,128)
    cudaFuncSetAttribute(fps_kernel, cudaFuncAttributeMaxDynamicSharedMemorySize, 98304);
    cudaFuncSetAttribute(mlp_kernel, cudaFuncAttributeMaxDynamicSharedMemorySize, 99328);
    prep_kernel<<<1, 128>>>((const float*)d_in[2], (const float*)d_in[3], (const float*)d_in[4],
                            (const float*)d_in[5], (const float*)d_in[6], (const float*)d_in[7],
                            (const float*)d_in[8], (const float*)d_in[9], (const float*)d_in[10],
                            (const float*)d_in[11], (const float*)d_in[12], (const float*)d_in[13],
                            (const float*)d_in[14], (const float*)d_in[15], (const float*)d_in[16],
                            (const float*)d_in[17], (const float*)d_in[18], (const float*)d_in[19]);
    fps_kernel<<<NB, 1024, 98304>>>(xyz, nxyz);
    ball_kernel<<<NB * 256, 256>>>(xyz, nxyz);
    mlp_kernel<<<NB * 256, 256, 99328>>>(xyz, pts, nxyz, npts);
}

// round 6
// speedup vs baseline: 1.3044x; 1.0686x over previous
// Round 6: FPS single-barrier packed-u64 argmax; MLP cout-split 2 blocks/SM.
#include <cuda_runtime.h>

#define NB 8
#define NN 8192
#define NS 2048

typedef unsigned long long u64;

#define PK2(d, lo, hi)   asm("mov.b64 %0, {%1,%2};" : "=l"(d) : "f"(lo), "f"(hi))
#define UPK2(lo, hi, v)  asm("mov.b64 {%0,%1}, %2;" : "=f"(lo), "=f"(hi) : "l"(v))
#define ADD2(d, a, b)    asm("add.rn.f32x2 %0, %1, %2;" : "=l"(d) : "l"(a), "l"(b))
#define MUL2(d, a, b)    asm("mul.rn.f32x2 %0, %1, %2;" : "=l"(d) : "l"(a), "l"(b))
#define FMA2(d, a, b, c) asm("fma.rn.f32x2 %0, %1, %2, %3;" : "=l"(d) : "l"(a), "l"(b), "l"(c))

// folded weights: w0t[9*64]@0 b0@576 w1t[64*64]@640 b1@4736 w2t[64*128]@4800 b2@12992
__device__ __align__(16) float g_w[13120];
__device__ int g_ball[NB * NS * 32];

__global__ void prep_kernel(const float* w0, const float* b0, const float* g0, const float* bt0, const float* m0, const float* v0,
                            const float* w1, const float* b1, const float* g1, const float* bt1, const float* m1, const float* v1,
                            const float* w2, const float* b2, const float* g2, const float* bt2, const float* m2, const float* v2) {
    int t = threadIdx.x;
    if (t < 64) {
        float s = g0[t] * rsqrtf(v0[t] + 1e-5f);
        for (int c = 0; c < 9; c++) g_w[c * 64 + t] = w0[t * 9 + c] * s;
        g_w[576 + t] = (b0[t] - m0[t]) * s + bt0[t];
        float s1 = g1[t] * rsqrtf(v1[t] + 1e-5f);
        for (int c = 0; c < 64; c++) g_w[640 + c * 64 + t] = w1[t * 64 + c] * s1;
        g_w[4736 + t] = (b1[t] - m1[t]) * s1 + bt1[t];
    }
    if (t < 128) {
        float s2 = g2[t] * rsqrtf(v2[t] + 1e-5f);
        for (int c = 0; c < 64; c++) g_w[4800 + c * 128 + t] = w2[t * 64 + c] * s2;
        g_w[12992 + t] = (b2[t] - m2[t]) * s2 + bt2[t];
    }
}

__global__ __launch_bounds__(1024, 1) void fps_kernel(const float* __restrict__ xyz, float* __restrict__ nxyz) {
    extern __shared__ float sx[];            // 24576 floats
    __shared__ u64 slot[4];
    int b = blockIdx.x, t = threadIdx.x;
    if (t < 4) slot[t] = 0ull;
    const float4* src = (const float4*)(xyz + (size_t)b * NN * 3);
    float4* d4 = (float4*)sx;
    for (int i = t; i < 6144; i += 1024) d4[i] = src[i];
    __syncthreads();
    // pair j holds points p0 = t + (2j)*1024 (lo) and p1 = p0 + 1024 (hi)
    u64 px2[4], py2[4], pz2[4];
    float dd[8];
#pragma unroll
    for (int j = 0; j < 4; j++) {
        int p0 = t + ((2 * j) << 10), p1 = p0 + 1024;
        PK2(px2[j], sx[p0 * 3 + 0], sx[p1 * 3 + 0]);
        PK2(py2[j], sx[p0 * 3 + 1], sx[p1 * 3 + 1]);
        PK2(pz2[j], sx[p0 * 3 + 2], sx[p1 * 3 + 2]);
        dd[2 * j] = 1e10f; dd[2 * j + 1] = 1e10f;
    }
    int far = 0;
    float* ob = nxyz + (size_t)b * NS * 3;
    for (int it = 0; it < NS; it++) {
        float cx = sx[far * 3], cy = sx[far * 3 + 1], cz = sx[far * 3 + 2];
        if (t == 0) { ob[it * 3] = cx; ob[it * 3 + 1] = cy; ob[it * 3 + 2] = cz; }
        if (t == 32) slot[(it + 2) & 3] = 0ull;   // reset slot two iterations ahead
        float ncx = -cx, ncy = -cy, ncz = -cz;
        u64 ncx2, ncy2, ncz2;
        PK2(ncx2, ncx, ncx); PK2(ncy2, ncy, ncy); PK2(ncz2, ncz, ncz);
        float bv = -1.f;
#pragma unroll
        for (int j = 0; j < 4; j++) {
            u64 dx, dy, dz, xx, yy, zz, s01;
            ADD2(dx, px2[j], ncx2);        // px - cx (exact: a + (-b) == a - b)
            ADD2(dy, py2[j], ncy2);
            ADD2(dz, pz2[j], ncz2);
            MUL2(xx, dx, dx);
            MUL2(yy, dy, dy);
            MUL2(zz, dz, dz);
            ADD2(s01, xx, yy);
            ADD2(s01, s01, zz);            // (x2+y2)+z2, same association as before
            float s0, s1;
            UPK2(s0, s1, s01);
            dd[2 * j]     = fminf(dd[2 * j], s0);
            dd[2 * j + 1] = fminf(dd[2 * j + 1], s1);
            bv = fmaxf(bv, dd[2 * j]);
            bv = fmaxf(bv, dd[2 * j + 1]);
        }
        float mymax = bv;
#pragma unroll
        for (int o = 16; o; o >>= 1) bv = fmaxf(bv, __shfl_xor_sync(~0u, bv, o));
        if (mymax == bv) {
            // smallest global index among this thread's ties (descending k keeps smallest)
            int p = 0;
#pragma unroll
            for (int k = 7; k >= 0; k--)
                if (dd[k] == mymax) p = t + (k << 10);
            u64 pk = ((u64)__float_as_uint(mymax) << 32) | (u64)(~(unsigned)p);
            atomicMax(&slot[it & 3], pk);
        }
        __syncthreads();
        far = (int)(~(unsigned)slot[it & 3]);
    }
}

__global__ __launch_bounds__(256) void ball_kernel(const float* __restrict__ xyz, const float* __restrict__ nxyz) {
    __shared__ float tile[6144];
    int b = blockIdx.x >> 8;
    int s = ((blockIdx.x & 255) << 3) + (threadIdx.x >> 5);
    int lane = threadIdx.x & 31;
    const float* nx = nxyz + (size_t)(b * NS + s) * 3;
    float cx = nx[0], cy = nx[1], cz = nx[2];
    float sn = cx * cx + cy * cy + cz * cz;
    const float R2 = 0.0625f, BIG = 1e30f;
    float kd = BIG; int ki = 0;
    float thr = BIG;
    for (int n0 = 0; n0 < NN; n0 += 2048) {
        __syncthreads();
        const float4* src = (const float4*)(xyz + (size_t)b * NN * 3 + n0 * 3);
        float4* d4 = (float4*)tile;
        for (int i = threadIdx.x; i < 1536; i += 256) d4[i] = src[i];
        __syncthreads();
        for (int c = 0; c < 2048; c += 32) {
            int p = c + lane;
            float x = tile[p * 3], y = tile[p * 3 + 1], z = tile[p * 3 + 2];
            float sp = x * x + y * y + z * z;
            float dot = x * cx + y * cy + z * cz;
            float d2 = sn + sp - 2.f * dot;
            unsigned m = __ballot_sync(~0u, d2 <= R2 && d2 < thr);
            while (m) {
                int sl = __ffs(m) - 1; m &= m - 1;
                float dv = __shfl_sync(~0u, d2, sl);
                if (dv < thr) {
                    float mv = kd; int mi = ki, ml = lane;
#pragma unroll
                    for (int o = 16; o; o >>= 1) {
                        float ov = __shfl_xor_sync(~0u, mv, o);
                        int oi = __shfl_xor_sync(~0u, mi, o);
                        int ol = __shfl_xor_sync(~0u, ml, o);
                        if (ov > mv || (ov == mv && (oi > mi || (oi == mi && ol > ml)))) { mv = ov; mi = oi; ml = ol; }
                    }
                    if (lane == ml) { kd = dv; ki = n0 + c + sl; }
                    float tv = kd;
#pragma unroll
                    for (int o = 16; o; o >>= 1) tv = fmaxf(tv, __shfl_xor_sync(~0u, tv, o));
                    thr = tv;
                }
            }
        }
    }
    float nv = kd; int ni = ki;
#pragma unroll
    for (int o = 16; o; o >>= 1) {
        float ov = __shfl_xor_sync(~0u, nv, o);
        int oi = __shfl_xor_sync(~0u, ni, o);
        if (ov < nv || (ov == nv && oi < ni)) { nv = ov; ni = oi; }
    }
    g_ball[((b * NS + s) << 5) + lane] = (kd >= BIG) ? ni : ki;
}

// SMEM: W[8448] | A0[4][64][32] | A1[4][64][32]  = 24832 floats = 99328 B
// warp = (group g = warp&3, cout-half h = warp>>2); lane = neighbor point.
__global__ __launch_bounds__(256, 2) void mlp_kernel(const float* __restrict__ xyz, const float* __restrict__ pts,
                                                     const float* __restrict__ nxyz, float* __restrict__ outp) {
    extern __shared__ float S[];
    float* W  = S;
    float* A0 = S + 8448;
    float* A1 = S + 16640;
    int tid = threadIdx.x;
    int warp = tid >> 5, lane = tid & 31;
    int g = warp & 3, h = warp >> 2;
    int gs = blockIdx.x * 4 + g;             // global sample index = b*NS + s
    {   // phase A: w0t,b0,w1t,b1 = 4800 floats
        const float4* g4 = (const float4*)g_w;
        float4* w4 = (float4*)W;
        for (int i = tid; i < 1200; i += 256) w4[i] = g4[i];
    }
    int gi = g_ball[(gs << 5) + lane];
    int bb = gs >> 11;
    const float* nx = nxyz + (size_t)gs * 3;
    const float* P = xyz + (size_t)(bb * NN + gi) * 3;
    const float2* Q = (const float2*)(pts + (size_t)(bb * NN + gi) * 6);
    float f[9];
    f[0] = P[0] - nx[0]; f[1] = P[1] - nx[1]; f[2] = P[2] - nx[2];
    float2 q0 = Q[0], q1 = Q[1], q2 = Q[2];
    f[3] = q0.x; f[4] = q0.y; f[5] = q1.x; f[6] = q1.y; f[7] = q2.x; f[8] = q2.y;
    __syncthreads();

    float* Ag0 = A0 + g * 2048;
    float* Ag1 = A1 + g * 2048;
    u64 acc[16];
    {   // layer1 9->64: this warp computes couts [h*32, h*32+32)
        const u64* bp = (const u64*)(W + 576 + h * 32);
#pragma unroll
        for (int q = 0; q < 16; q++) acc[q] = bp[q];
#pragma unroll
        for (int c = 0; c < 9; c++) {
            u64 xx; PK2(xx, f[c], f[c]);
            const ulonglong2* wr = (const ulonglong2*)(W + c * 64 + h * 32);
#pragma unroll
            for (int q = 0; q < 8; q++) {
                ulonglong2 w = wr[q];
                FMA2(acc[2 * q], xx, w.x, acc[2 * q]);
                FMA2(acc[2 * q + 1], xx, w.y, acc[2 * q + 1]);
            }
        }
#pragma unroll
        for (int q = 0; q < 16; q++) {
            float r0, r1; UPK2(r0, r1, acc[q]);
            Ag0[(h * 32 + 2 * q) * 32 + lane]     = fmaxf(r0, 0.f);
            Ag0[(h * 32 + 2 * q + 1) * 32 + lane] = fmaxf(r1, 0.f);
        }
    }
    __syncthreads();
    {   // layer2 64->64
        const u64* bp = (const u64*)(W + 4736 + h * 32);
#pragma unroll
        for (int q = 0; q < 16; q++) acc[q] = bp[q];
#pragma unroll 8
        for (int c = 0; c < 64; c++) {
            float xv = Ag0[c * 32 + lane];
            u64 xx; PK2(xx, xv, xv);
            const ulonglong2* wr = (const ulonglong2*)(W + 640 + c * 64 + h * 32);
#pragma unroll
            for (int q = 0; q < 8; q++) {
                ulonglong2 w = wr[q];
                FMA2(acc[2 * q], xx, w.x, acc[2 * q]);
                FMA2(acc[2 * q + 1], xx, w.y, acc[2 * q + 1]);
            }
        }
#pragma unroll
        for (int q = 0; q < 16; q++) {
            float r0, r1; UPK2(r0, r1, acc[q]);
            Ag1[(h * 32 + 2 * q) * 32 + lane]     = fmaxf(r0, 0.f);
            Ag1[(h * 32 + 2 * q + 1) * 32 + lane] = fmaxf(r1, 0.f);
        }
    }
    __syncthreads();
    {   // phase B weights: w2t,b2 = 8320 floats
        const float4* g4 = (const float4*)(g_w + 4800);
        float4* w4 = (float4*)W;
        for (int i = tid; i < 2080; i += 256) w4[i] = g4[i];
    }
    __syncthreads();
    float* orow = outp + (size_t)gs * 128;
#pragma unroll 1
    for (int sub = 0; sub < 2; sub++) {  // layer3 64->128: this warp covers couts [h*64, h*64+64)
        int cb = h * 64 + sub * 32;
        const u64* bp = (const u64*)(W + 8192 + cb);
#pragma unroll
        for (int q = 0; q < 16; q++) acc[q] = bp[q];
#pragma unroll 8
        for (int c = 0; c < 64; c++) {
            float xv = Ag1[c * 32 + lane];
            u64 xx; PK2(xx, xv, xv);
            const ulonglong2* wr = (const ulonglong2*)(W + c * 128 + cb);
#pragma unroll
            for (int q = 0; q < 8; q++) {
                ulonglong2 w = wr[q];
                FMA2(acc[2 * q], xx, w.x, acc[2 * q]);
                FMA2(acc[2 * q + 1], xx, w.y, acc[2 * q + 1]);
            }
        }
        float v[32];
#pragma unroll
        for (int q = 0; q < 16; q++) UPK2(v[2 * q], v[2 * q + 1], acc[q]);
        // halving butterfly: after all stages, v[0] on lane l = max over lanes of cout cb+l
#pragma unroll
        for (int o = 16; o; o >>= 1) {
#pragma unroll
            for (int j = 0; j < o; j++) {
                float xj   = (lane & o) ? v[j] : v[j + o];
                float r    = __shfl_xor_sync(~0u, xj, o);
                float mine = (lane & o) ? v[j + o] : v[j];
                v[j] = fmaxf(mine, r);
            }
        }
        orow[cb + lane] = fmaxf(v[0], 0.f);
    }
}

extern "C" void kernel_launch(void* const* d_in, const int* in_sizes, int n_in,
                              void* d_out, int out_size) {
    const float* xyz = (const float*)d_in[0];
    const float* pts = (const float*)d_in[1];
    float* out = (float*)d_out;
    float* nxyz = out;                       // (B,S,3)
    float* npts = out + NB * NS * 3;         // (B,S,128)
    cudaFuncSetAttribute(fps_kernel, cudaFuncAttributeMaxDynamicSharedMemorySize, 98304);
    cudaFuncSetAttribute(mlp_kernel, cudaFuncAttributeMaxDynamicSharedMemorySize, 99328);
    prep_kernel<<<1, 128>>>((const float*)d_in[2], (const float*)d_in[3], (const float*)d_in[4],
                            (const float*)d_in[5], (const float*)d_in[6], (const float*)d_in[7],
                            (const float*)d_in[8], (const float*)d_in[9], (const float*)d_in[10],
                            (const float*)d_in[11], (const float*)d_in[12], (const float*)d_in[13],
                            (const float*)d_in[14], (const float*)d_in[15], (const float*)d_in[16],
                            (const float*)d_in[17], (const float*)d_in[18], (const float*)d_in[19]);
    fps_kernel<<<NB, 1024, 98304>>>(xyz, nxyz);
    ball_kernel<<<NB * 256, 256>>>(xyz, nxyz);
    mlp_kernel<<<NB * 1024 / 2, 256, 99328>>>(xyz, pts, nxyz, npts);
}